// round 2
// baseline (speedup 1.0000x reference)
#include <cuda_runtime.h>
#include <cuda_bf16.h>
#include <cuda_fp8.h>
#include <cstdint>

// Problem shapes (fixed by the dataset): M=16384, K=4096, N=4096
// Scratch: quantized activation (bf16 holding exact e4m3 values) + bf16 weight.
__device__ __nv_bfloat16 g_qx[67108864];   // 16384*4096  (128 MiB)
__device__ __nv_bfloat16 g_qw[16777216];   // 4096*4096   (32 MiB)
__device__ unsigned int  g_amax_bits;

static __device__ __forceinline__ uint32_t smem_u32(const void* p) {
    return (uint32_t)__cvta_generic_to_shared(p);
}

// ---------------------------------------------------------------------------
// 1) amax reduction
// ---------------------------------------------------------------------------
__global__ void init_amax_kernel() { g_amax_bits = 0u; }

__global__ void amax_kernel(const float* __restrict__ x, int n4) {
    const float4* x4 = (const float4*)x;
    float m = 0.0f;
    for (int i = blockIdx.x * blockDim.x + threadIdx.x; i < n4;
         i += gridDim.x * blockDim.x) {
        float4 v = x4[i];
        m = fmaxf(m, fabsf(v.x));
        m = fmaxf(m, fabsf(v.y));
        m = fmaxf(m, fabsf(v.z));
        m = fmaxf(m, fabsf(v.w));
    }
#pragma unroll
    for (int o = 16; o > 0; o >>= 1)
        m = fmaxf(m, __shfl_xor_sync(0xffffffffu, m, o));
    if ((threadIdx.x & 31) == 0)
        atomicMax(&g_amax_bits, __float_as_uint(m));  // m >= 0: int-order == float-order
}

// ---------------------------------------------------------------------------
// 2) quantize x: e4m3 satfinite RN (matches jnp clip+astype), stored as bf16
// ---------------------------------------------------------------------------
static __device__ __forceinline__ unsigned short f2q_bf16(float v) {
    __nv_fp8_e4m3 q(v);                      // RN + saturate to +-448
    float f = float(q);                      // exact expansion
    __nv_bfloat16 b = __float2bfloat16_rn(f); // exact (e4m3 subset of bf16)
    return *reinterpret_cast<unsigned short*>(&b);
}

__global__ void quantize_x_kernel(const float* __restrict__ x, int n4) {
    float amax = fmaxf(__uint_as_float(g_amax_bits), 1e-12f);
    float s = 448.0f / amax;
    const float4* x4 = (const float4*)x;
    ushort4* q4 = (ushort4*)g_qx;
    for (int i = blockIdx.x * blockDim.x + threadIdx.x; i < n4;
         i += gridDim.x * blockDim.x) {
        float4 v = x4[i];
        ushort4 o;
        o.x = f2q_bf16(v.x * s);
        o.y = f2q_bf16(v.y * s);
        o.z = f2q_bf16(v.z * s);
        o.w = f2q_bf16(v.w * s);
        q4[i] = o;
    }
}

// qweight already holds exact e4m3 values in f32 -> bf16 conversion is exact.
__global__ void convert_w_kernel(const float* __restrict__ w, int n4) {
    const float4* w4 = (const float4*)w;
    ushort4* q4 = (ushort4*)g_qw;
    for (int i = blockIdx.x * blockDim.x + threadIdx.x; i < n4;
         i += gridDim.x * blockDim.x) {
        float4 v = w4[i];
        ushort4 o;
        __nv_bfloat16 b;
        b = __float2bfloat16_rn(v.x); o.x = *(unsigned short*)&b;
        b = __float2bfloat16_rn(v.y); o.y = *(unsigned short*)&b;
        b = __float2bfloat16_rn(v.z); o.z = *(unsigned short*)&b;
        b = __float2bfloat16_rn(v.w); o.w = *(unsigned short*)&b;
        q4[i] = o;
    }
}

// ---------------------------------------------------------------------------
// 3) GEMM: D[M,N] = qx[M,K] @ qw[N,K]^T, epilogue *= (amax/448)*w_scale, +bias
//    128x128x64 block tile, 8 warps (4 x 2), warp tile 32x64, mma m16n8k16 bf16.
// ---------------------------------------------------------------------------
#define BM 128
#define BN 128
#define BK 64
#define SSTR 72  // padded smem row stride in bf16 (conflict-free ldmatrix)

__global__ __launch_bounds__(256, 2)
void gemm_kernel(const float* __restrict__ bias,
                 const float* __restrict__ w_scale,
                 float* __restrict__ C, int M, int N, int K) {
    __shared__ __nv_bfloat16 As[BM][SSTR];
    __shared__ __nv_bfloat16 Bs[BN][SSTR];

    const int tid  = threadIdx.x;
    const int warp = tid >> 5;
    const int lane = tid & 31;
    const int wm   = warp >> 1;   // 0..3 -> 32-row warp tile
    const int wn   = warp & 1;    // 0..1 -> 64-col warp tile
    const int bm   = blockIdx.y * BM;
    const int bn   = blockIdx.x * BN;

    const __nv_bfloat16* A = g_qx;
    const __nv_bfloat16* B = g_qw;

    // Global-load mapping: 128 rows x 64 cols per tile = 1024 x (8 bf16) vectors
    const int lr = tid >> 3;        // base row 0..31 (4 rows per thread, +32 apart)
    const int lc = (tid & 7) * 8;   // col within BK

    float acc[2][8][4];
#pragma unroll
    for (int a = 0; a < 2; a++)
#pragma unroll
        for (int b = 0; b < 8; b++)
#pragma unroll
            for (int c = 0; c < 4; c++) acc[a][b][c] = 0.0f;

    uint4 pa[4], pb[4];

    // prologue load (k0 = 0)
#pragma unroll
    for (int i = 0; i < 4; i++) {
        int r = lr + i * 32;
        pa[i] = *(const uint4*)(A + (size_t)(bm + r) * K + lc);
        pb[i] = *(const uint4*)(B + (size_t)(bn + r) * K + lc);
    }
#pragma unroll
    for (int i = 0; i < 4; i++) {
        int r = lr + i * 32;
        *(uint4*)(&As[r][lc]) = pa[i];
        *(uint4*)(&Bs[r][lc]) = pb[i];
    }
    __syncthreads();

    for (int k0 = BK; k0 <= K; k0 += BK) {
        if (k0 < K) {
#pragma unroll
            for (int i = 0; i < 4; i++) {
                int r = lr + i * 32;
                pa[i] = *(const uint4*)(A + (size_t)(bm + r) * K + k0 + lc);
                pb[i] = *(const uint4*)(B + (size_t)(bn + r) * K + k0 + lc);
            }
        }

        // compute on current smem tile
#pragma unroll
        for (int kk = 0; kk < 4; kk++) {
            const int ko = kk * 16;
            uint32_t af[2][4];
            uint32_t bf[8][2];
#pragma unroll
            for (int mt = 0; mt < 2; mt++) {
                int row = wm * 32 + mt * 16 + (lane & 15);
                int col = ko + (lane >> 4) * 8;
                uint32_t addr = smem_u32(&As[row][col]);
                asm volatile(
                    "ldmatrix.sync.aligned.m8n8.x4.shared.b16 {%0,%1,%2,%3}, [%4];"
                    : "=r"(af[mt][0]), "=r"(af[mt][1]), "=r"(af[mt][2]), "=r"(af[mt][3])
                    : "r"(addr));
            }
#pragma unroll
            for (int p = 0; p < 4; p++) {
                int row = wn * 64 + p * 16 + ((lane >> 4) << 3) + (lane & 7);
                int col = ko + ((lane >> 3) & 1) * 8;
                uint32_t addr = smem_u32(&Bs[row][col]);
                uint32_t r0, r1, r2, r3;
                asm volatile(
                    "ldmatrix.sync.aligned.m8n8.x4.shared.b16 {%0,%1,%2,%3}, [%4];"
                    : "=r"(r0), "=r"(r1), "=r"(r2), "=r"(r3)
                    : "r"(addr));
                bf[2 * p + 0][0] = r0; bf[2 * p + 0][1] = r1;
                bf[2 * p + 1][0] = r2; bf[2 * p + 1][1] = r3;
            }
#pragma unroll
            for (int mt = 0; mt < 2; mt++) {
#pragma unroll
                for (int nt = 0; nt < 8; nt++) {
                    asm volatile(
                        "mma.sync.aligned.m16n8k16.row.col.f32.bf16.bf16.f32 "
                        "{%0,%1,%2,%3}, {%4,%5,%6,%7}, {%8,%9}, {%0,%1,%2,%3};"
                        : "+f"(acc[mt][nt][0]), "+f"(acc[mt][nt][1]),
                          "+f"(acc[mt][nt][2]), "+f"(acc[mt][nt][3])
                        : "r"(af[mt][0]), "r"(af[mt][1]), "r"(af[mt][2]), "r"(af[mt][3]),
                          "r"(bf[nt][0]), "r"(bf[nt][1]));
                }
            }
        }

        __syncthreads();
        if (k0 < K) {
#pragma unroll
            for (int i = 0; i < 4; i++) {
                int r = lr + i * 32;
                *(uint4*)(&As[r][lc]) = pa[i];
                *(uint4*)(&Bs[r][lc]) = pb[i];
            }
            __syncthreads();
        }
    }

    // epilogue: out = acc * (x_scale * w_scale) + bias
    float amax = fmaxf(__uint_as_float(g_amax_bits), 1e-12f);
    float s = 448.0f / amax;
    float xscale = 1.0f / s;                 // matches reference 1.0/s
    float total = xscale * __ldg(w_scale);

#pragma unroll
    for (int mt = 0; mt < 2; mt++) {
        int r0 = bm + wm * 32 + mt * 16 + (lane >> 2);
#pragma unroll
        for (int nt = 0; nt < 8; nt++) {
            int c = bn + wn * 64 + nt * 8 + (lane & 3) * 2;
            float b0 = __ldg(&bias[c]);
            float b1 = __ldg(&bias[c + 1]);
            float2 v0, v1;
            v0.x = acc[mt][nt][0] * total + b0;
            v0.y = acc[mt][nt][1] * total + b1;
            v1.x = acc[mt][nt][2] * total + b0;
            v1.y = acc[mt][nt][3] * total + b1;
            *(float2*)(C + (size_t)r0 * N + c)       = v0;
            *(float2*)(C + (size_t)(r0 + 8) * N + c) = v1;
        }
    }
}

// ---------------------------------------------------------------------------
extern "C" void kernel_launch(void* const* d_in, const int* in_sizes, int n_in,
                              void* d_out, int out_size) {
    const float* x       = (const float*)d_in[0];
    const float* w       = (const float*)d_in[1];
    const float* w_scale = (const float*)d_in[2];
    const float* bias    = (const float*)d_in[3];
    float* out           = (float*)d_out;

    int N = in_sizes[3];
    int K = in_sizes[1] / N;
    int M = in_sizes[0] / K;
    int nx4 = (M * K) / 4;
    int nw4 = (N * K) / 4;

    init_amax_kernel<<<1, 1>>>();
    amax_kernel<<<2048, 256>>>(x, nx4);
    quantize_x_kernel<<<2048, 256>>>(x, nx4);
    convert_w_kernel<<<1024, 256>>>(w, nw4);

    dim3 grid(N / BN, M / BM);
    gemm_kernel<<<grid, 256>>>(bias, w_scale, out, M, N, K);
}

// round 5
// speedup vs baseline: 1.0574x; 1.0574x over previous
#include <cuda_runtime.h>
#include <cuda_bf16.h>
#include <cuda_fp8.h>
#include <cstdint>

// Shapes fixed by dataset: M=16384, K=4096, N=4096
// Scratch: e4m3 bytes for activation and weight.
__device__ uint8_t g_qx[67108864];   // 16384*4096 bytes
__device__ uint8_t g_qw[16777216];   // 4096*4096 bytes
__device__ unsigned int g_amax_bits;

static __device__ __forceinline__ uint32_t smem_u32(const void* p) {
    return (uint32_t)__cvta_generic_to_shared(p);
}

// ---------------------------------------------------------------------------
// 1) amax reduction
// ---------------------------------------------------------------------------
__global__ void init_amax_kernel() { g_amax_bits = 0u; }

__global__ void amax_kernel(const float* __restrict__ x, int n4) {
    const float4* x4 = (const float4*)x;
    float m = 0.0f;
    for (int i = blockIdx.x * blockDim.x + threadIdx.x; i < n4;
         i += gridDim.x * blockDim.x) {
        float4 v = x4[i];
        m = fmaxf(m, fabsf(v.x)); m = fmaxf(m, fabsf(v.y));
        m = fmaxf(m, fabsf(v.z)); m = fmaxf(m, fabsf(v.w));
    }
#pragma unroll
    for (int o = 16; o > 0; o >>= 1)
        m = fmaxf(m, __shfl_xor_sync(0xffffffffu, m, o));
    if ((threadIdx.x & 31) == 0)
        atomicMax(&g_amax_bits, __float_as_uint(m)); // m >= 0
}

// ---------------------------------------------------------------------------
// 2) quantize x -> e4m3 bytes (satfinite RN == jnp clip+astype)
// ---------------------------------------------------------------------------
__global__ void quantize_x_kernel(const float* __restrict__ x, int n4) {
    float amax = fmaxf(__uint_as_float(g_amax_bits), 1e-12f);
    float s = 448.0f / amax;
    const float4* x4 = (const float4*)x;
    uchar4* q4 = (uchar4*)g_qx;
    for (int i = blockIdx.x * blockDim.x + threadIdx.x; i < n4;
         i += gridDim.x * blockDim.x) {
        float4 v = x4[i];
        uchar4 o;
        o.x = __nv_fp8_e4m3(v.x * s).__x;
        o.y = __nv_fp8_e4m3(v.y * s).__x;
        o.z = __nv_fp8_e4m3(v.z * s).__x;
        o.w = __nv_fp8_e4m3(v.w * s).__x;
        q4[i] = o;
    }
}

// qweight f32 already holds exact e4m3 values -> byte conversion exact
__global__ void convert_w_kernel(const float* __restrict__ w, int n4) {
    const float4* w4 = (const float4*)w;
    uchar4* q4 = (uchar4*)g_qw;
    for (int i = blockIdx.x * blockDim.x + threadIdx.x; i < n4;
         i += gridDim.x * blockDim.x) {
        float4 v = w4[i];
        uchar4 o;
        o.x = __nv_fp8_e4m3(v.x).__x;
        o.y = __nv_fp8_e4m3(v.y).__x;
        o.z = __nv_fp8_e4m3(v.z).__x;
        o.w = __nv_fp8_e4m3(v.w).__x;
        q4[i] = o;
    }
}

// ---------------------------------------------------------------------------
// 3) fp8 GEMM via mma.sync m16n8k32 e4m3:
//    128x128 CTA tile, BK=64 bytes/chunk, 4-stage cp.async pipeline,
//    8 warps (4x2), warp tile 32x64. Epilogue: *= (amax/448)*w_scale, + bias.
// ---------------------------------------------------------------------------
#define BM 128
#define BN 128
#define BKB 64                  // K bytes per chunk (= k64 in fp8)
#define STAGES 4
#define RSTR 80                 // padded smem row stride in bytes (16B aligned)
#define A_STAGE (BM * RSTR)     // 10240
#define B_STAGE (BN * RSTR)     // 10240
#define STAGE_BYTES (A_STAGE + B_STAGE)             // 20480
#define SMEM_TOTAL (STAGES * STAGE_BYTES)           // 81920

static __device__ __forceinline__ void cp16(uint32_t dst, const void* src) {
    asm volatile("cp.async.cg.shared.global [%0], [%1], 16;"
                 :: "r"(dst), "l"(src) : "memory");
}

static __device__ __forceinline__ void load_stage(
    uint32_t sbase, int stage, const uint8_t* A, const uint8_t* B,
    int bm, int bn, int k0, int K, int tid) {
    uint32_t abase = sbase + stage * STAGE_BYTES;
    uint32_t bbase = abase + A_STAGE;
    // 128 rows x 4 16B vectors each for A and B; 256 threads -> 2 vec each
#pragma unroll
    for (int i = 0; i < 2; i++) {
        int id = i * 256 + tid;
        int row = id >> 2, c16 = (id & 3) * 16;
        cp16(abase + row * RSTR + c16, A + (size_t)(bm + row) * K + k0 + c16);
    }
#pragma unroll
    for (int i = 0; i < 2; i++) {
        int id = i * 256 + tid;
        int row = id >> 2, c16 = (id & 3) * 16;
        cp16(bbase + row * RSTR + c16, B + (size_t)(bn + row) * K + k0 + c16);
    }
}

__global__ __launch_bounds__(256, 2)
void gemm_kernel(const float* __restrict__ bias,
                 const float* __restrict__ w_scale,
                 float* __restrict__ C, int M, int N, int K) {
    extern __shared__ char smem[];
    const uint32_t sbase = smem_u32(smem);
    const int tid  = threadIdx.x;
    const int warp = tid >> 5;
    const int lane = tid & 31;
    const int wm   = warp >> 1;   // 0..3: 32-row warp tile
    const int wn   = warp & 1;    // 0..1: 64-col warp tile
    const int bm   = blockIdx.y * BM;
    const int bn   = blockIdx.x * BN;
    const int NCHUNK = K / BKB;   // 64

    const uint8_t* A = g_qx;
    const uint8_t* B = g_qw;

    float acc[2][8][4];
#pragma unroll
    for (int a = 0; a < 2; a++)
#pragma unroll
        for (int b = 0; b < 8; b++)
#pragma unroll
            for (int c = 0; c < 4; c++) acc[a][b][c] = 0.0f;

    // prologue: stages 0..2
#pragma unroll
    for (int c = 0; c < STAGES - 1; c++) {
        load_stage(sbase, c, A, B, bm, bn, c * BKB, K, tid);
        asm volatile("cp.async.commit_group;" ::: "memory");
    }

    for (int c = 0; c < NCHUNK; c++) {
        asm volatile("cp.async.wait_group %0;" :: "n"(STAGES - 2) : "memory");
        __syncthreads();

        // issue loads for chunk c+3 into stage (c+3)%4 (consumed at c-1; safe)
        if (c + STAGES - 1 < NCHUNK)
            load_stage(sbase, (c + STAGES - 1) % STAGES, A, B, bm, bn,
                       (c + STAGES - 1) * BKB, K, tid);
        asm volatile("cp.async.commit_group;" ::: "memory");

        const uint32_t abase = sbase + (c % STAGES) * STAGE_BYTES;
        const uint32_t bbase = abase + A_STAGE;

#pragma unroll
        for (int ks = 0; ks < 2; ks++) {      // two k32 steps per 64B chunk
            const int kb = ks * 32;           // byte offset within row
            uint32_t af[2][4];
            uint32_t bf[8][2];
#pragma unroll
            for (int mt = 0; mt < 2; mt++) {
                int row = wm * 32 + mt * 16 + (lane & 15);
                int col = kb + (lane >> 4) * 16;
                uint32_t addr = abase + row * RSTR + col;
                asm volatile(
                    "ldmatrix.sync.aligned.m8n8.x4.shared.b16 {%0,%1,%2,%3}, [%4];"
                    : "=r"(af[mt][0]), "=r"(af[mt][1]),
                      "=r"(af[mt][2]), "=r"(af[mt][3])
                    : "r"(addr));
            }
#pragma unroll
            for (int p = 0; p < 4; p++) {
                int row = wn * 64 + p * 16 + ((lane >> 4) << 3) + (lane & 7);
                int col = kb + ((lane >> 3) & 1) * 16;
                uint32_t addr = bbase + row * RSTR + col;
                uint32_t r0, r1, r2, r3;
                asm volatile(
                    "ldmatrix.sync.aligned.m8n8.x4.shared.b16 {%0,%1,%2,%3}, [%4];"
                    : "=r"(r0), "=r"(r1), "=r"(r2), "=r"(r3)
                    : "r"(addr));
                bf[2 * p + 0][0] = r0; bf[2 * p + 0][1] = r1;
                bf[2 * p + 1][0] = r2; bf[2 * p + 1][1] = r3;
            }
#pragma unroll
            for (int mt = 0; mt < 2; mt++) {
#pragma unroll
                for (int nt = 0; nt < 8; nt++) {
                    asm volatile(
                        "mma.sync.aligned.m16n8k32.row.col.f32.e4m3.e4m3.f32 "
                        "{%0,%1,%2,%3}, {%4,%5,%6,%7}, {%8,%9}, {%0,%1,%2,%3};"
                        : "+f"(acc[mt][nt][0]), "+f"(acc[mt][nt][1]),
                          "+f"(acc[mt][nt][2]), "+f"(acc[mt][nt][3])
                        : "r"(af[mt][0]), "r"(af[mt][1]),
                          "r"(af[mt][2]), "r"(af[mt][3]),
                          "r"(bf[nt][0]), "r"(bf[nt][1]));
                }
            }
        }
    }

    // epilogue: out = acc * (x_scale * w_scale) + bias
    float amax = fmaxf(__uint_as_float(g_amax_bits), 1e-12f);
    float sq = 448.0f / amax;
    float total = (1.0f / sq) * __ldg(w_scale);

#pragma unroll
    for (int mt = 0; mt < 2; mt++) {
        int r0 = bm + wm * 32 + mt * 16 + (lane >> 2);
#pragma unroll
        for (int nt = 0; nt < 8; nt++) {
            int cix = bn + wn * 64 + nt * 8 + (lane & 3) * 2;
            float b0 = __ldg(&bias[cix]);
            float b1 = __ldg(&bias[cix + 1]);
            float2 v0, v1;
            v0.x = acc[mt][nt][0] * total + b0;
            v0.y = acc[mt][nt][1] * total + b1;
            v1.x = acc[mt][nt][2] * total + b0;
            v1.y = acc[mt][nt][3] * total + b1;
            *(float2*)(C + (size_t)r0 * N + cix)       = v0;
            *(float2*)(C + (size_t)(r0 + 8) * N + cix) = v1;
        }
    }
}

// ---------------------------------------------------------------------------
extern "C" void kernel_launch(void* const* d_in, const int* in_sizes, int n_in,
                              void* d_out, int out_size) {
    const float* x       = (const float*)d_in[0];
    const float* w       = (const float*)d_in[1];
    const float* w_scale = (const float*)d_in[2];
    const float* bias    = (const float*)d_in[3];
    float* out           = (float*)d_out;

    int N = in_sizes[3];
    int K = in_sizes[1] / N;
    int M = in_sizes[0] / K;
    int nx4 = (M * K) / 4;
    int nw4 = (N * K) / 4;

    cudaFuncSetAttribute(gemm_kernel,
                         cudaFuncAttributeMaxDynamicSharedMemorySize, SMEM_TOTAL);

    init_amax_kernel<<<1, 1>>>();
    amax_kernel<<<2048, 256>>>(x, nx4);
    quantize_x_kernel<<<2048, 256>>>(x, nx4);
    convert_w_kernel<<<1024, 256>>>(w, nw4);

    dim3 grid(N / BN, M / BM);
    gemm_kernel<<<grid, 256, SMEM_TOTAL>>>(bias, w_scale, out, M, N, K);
}